// round 6
// baseline (speedup 1.0000x reference)
#include <cuda_runtime.h>
#include <cuda_bf16.h>

// YOLOv1 loss — persistent blocks, WARP-autonomous register-landing pipeline.
// Each warp: 32-cell tiles, private smem region, next tile's 15 LDG.128 in
// flight through compute. No block barriers in the hot loop.
// Argmax over t[10:30] via order-preserving tree (depth 5, first-max exact).

#define NCELL  (16384 * 7 * 7)       // 802816
#define BLK    128
#define WARPS  4
#define BPSM   5
#define GRID   (148 * BPSM)          // 740 persistent blocks
#define WTILE  32                    // cells per warp-tile
#define NWT    (NCELL / WTILE)       // 25088
#define WSTRIDE (GRID * WARPS)       // 2960 warps
#define WFL    (WTILE * 30)          // floats per tensor per warp-tile (960)
#define WF4    (WFL / 4)             // float4 per tensor (240)
#define NLD    15                    // float4 per thread (2*WF4/32)

__device__ float4 g_part[GRID];
__device__ unsigned int g_count = 0;

__global__ __launch_bounds__(BLK, BPSM)
void yolo_fused(const float* __restrict__ P,
                const float* __restrict__ T,
                float* __restrict__ out)
{
    __shared__ float buf[WARPS][2 * WFL];   // per-warp [P(960)|T(960)] = 7680 B
    const int tid  = threadIdx.x;
    const int wid  = tid >> 5;
    const int lane = tid & 31;
    const float CELL = 1.0f / 7.0f;

    float ax = 0.0f, ay = 0.0f, az = 0.0f, aw = 0.0f;
    float4 r[NLD];                    // landing zone for next warp-tile

    const int gw = blockIdx.x * WARPS + wid;   // global warp id (< WSTRIDE)
    // prologue: load first warp-tile into regs (front-batched LDG.128)
    {
        const float4* gp = (const float4*)(P + (size_t)gw * WFL);
        const float4* gt = (const float4*)(T + (size_t)gw * WFL);
        #pragma unroll
        for (int i = 0; i < NLD; ++i) {
            const int idx = lane + i * 32;          // 0..479
            r[i] = (idx < WF4) ? __ldg(gp + idx) : __ldg(gt + (idx - WF4));
        }
    }

    for (int wt = gw; wt < NWT; wt += WSTRIDE) {
        // deposit current tile's regs into this warp's smem region
        float4* b4 = (float4*)buf[wid];
        #pragma unroll
        for (int i = 0; i < NLD; ++i) b4[lane + i * 32] = r[i];

        // issue next tile's loads NOW — in flight through compute below
        const int nx = wt + WSTRIDE;
        if (nx < NWT) {
            const float4* gp = (const float4*)(P + (size_t)nx * WFL);
            const float4* gt = (const float4*)(T + (size_t)nx * WFL);
            #pragma unroll
            for (int i = 0; i < NLD; ++i) {
                const int idx = lane + i * 32;
                r[i] = (idx < WF4) ? __ldg(gp + idx) : __ldg(gt + (idx - WF4));
            }
        }
        __syncwarp();                 // warp's smem stage fully written

        const float* p = buf[wid] + lane * 30;
        const float* t = p + WFL;

        const float t0 = t[0], t1 = t[1], t2 = t[2], t3 = t[3], tc = t[4];

        // target corners — faithful to the reference's in-place bug:
        //   xy1 = xy*CELL - wh*0.5 ;  xy2 = xy1*CELL + wh*0.5
        const float twx = t2 * t2, twy = t3 * t3;
        const float tx1 = t0 * CELL - 0.5f * twx;
        const float ty1 = t1 * CELL - 0.5f * twy;
        const float tx2 = tx1 * CELL + 0.5f * twx;
        const float ty2 = ty1 * CELL + 0.5f * twy;
        const float area_t = (tx2 - tx1) * (ty2 - ty1);

        float iou0, iou1;
        #pragma unroll
        for (int b = 0; b < 2; ++b) {
            const float px = p[b * 5 + 0], py = p[b * 5 + 1];
            const float pw = p[b * 5 + 2], ph = p[b * 5 + 3];
            const float pwx = pw * pw, pwy = ph * ph;
            const float x1 = px * CELL - 0.5f * pwx;
            const float y1 = py * CELL - 0.5f * pwy;
            const float x2 = x1 * CELL + 0.5f * pwx;
            const float y2 = y1 * CELL + 0.5f * pwy;
            const float ltx = fmaxf(x1, tx1), lty = fmaxf(y1, ty1);
            const float rbx = fminf(x2, tx2), rby = fminf(y2, ty2);
            const float dx = fmaxf(rbx - ltx, 0.0f);
            const float dy = fmaxf(rby - lty, 0.0f);
            const float inter  = dx * dy;
            const float area_p = (x2 - x1) * (y2 - y1);
            const float v = inter / (area_p + area_t - inter);
            if (b == 0) iou0 = v; else iou1 = v;
        }
        const int b5 = (iou1 > iou0) ? 5 : 0;     // first max wins ties

        // argmax over t[10:30] — order-preserving tree (adjacent pairing at
        // every level keeps index sets contiguous & ordered, so 'strictly
        // greater picks right' is exactly first-max).
        float av[10]; int ak[10];
        #pragma unroll
        for (int k = 0; k < 10; ++k) {
            const float a = t[10 + 2 * k], b = t[11 + 2 * k];
            const bool g = b > a;
            av[k] = g ? b : a;
            ak[k] = 10 + 2 * k + (g ? 1 : 0);
        }
        #pragma unroll
        for (int k = 0; k < 5; ++k) {
            const bool g = av[2 * k + 1] > av[2 * k];
            av[k] = g ? av[2 * k + 1] : av[2 * k];
            ak[k] = g ? ak[2 * k + 1] : ak[2 * k];
        }
        { const bool g = av[1] > av[0]; av[0] = g ? av[1] : av[0]; ak[0] = g ? ak[1] : ak[0]; }
        { const bool g = av[3] > av[2]; av[2] = g ? av[3] : av[2]; ak[2] = g ? ak[3] : ak[2]; }
        { const bool g = av[2] > av[0]; av[0] = g ? av[2] : av[0]; ak[0] = g ? ak[2] : ak[0]; }
        { const bool g = av[4] > av[0]; av[0] = g ? av[4] : av[0]; ak[0] = g ? ak[4] : ak[0]; }
        const int   kcol = ak[0];
        const float tmax = av[0];     // == t[kcol]

        const bool obj = (tc == 1.0f);
        const bool noo = (tc == 0.0f);

        const float dk = p[kcol]   - tmax;
        const float dc = p[b5 + 4] - t[b5 + 4];
        const float d0 = p[b5 + 0] - t[b5 + 0];
        const float d1 = p[b5 + 1] - t[b5 + 1];
        const float d2 = p[b5 + 2] - t[b5 + 2];
        const float d3 = p[b5 + 3] - t[b5 + 3];
        const float d4 = p[4] - tc;
        const float d9 = p[9] - t[9];

        if (obj) {
            ax += dk * dk;                                   // cls
            ay += dc * dc;                                   // conf
            az += d0 * d0 + d1 * d1 + d2 * d2 + d3 * d3;     // center+wh
        }
        if (noo) aw += d4 * d4 + d9 * d9;                    // noobj

        __syncwarp();                 // all lanes done reading this stage
    }

    // ---- block reduce (once per block) ----
    #pragma unroll
    for (int o = 16; o > 0; o >>= 1) {
        ax += __shfl_down_sync(0xffffffffu, ax, o);
        ay += __shfl_down_sync(0xffffffffu, ay, o);
        az += __shfl_down_sync(0xffffffffu, az, o);
        aw += __shfl_down_sync(0xffffffffu, aw, o);
    }
    __shared__ float4 wsum[WARPS];
    __shared__ bool s_last;
    if (lane == 0) wsum[wid] = make_float4(ax, ay, az, aw);
    __syncthreads();
    if (tid == 0) {
        float4 sv = wsum[0];
        #pragma unroll
        for (int w = 1; w < WARPS; ++w) {
            sv.x += wsum[w].x; sv.y += wsum[w].y;
            sv.z += wsum[w].z; sv.w += wsum[w].w;
        }
        __stcg(&g_part[blockIdx.x], sv);
        __threadfence();
        unsigned int prev = atomicAdd(&g_count, 1u);
        s_last = (prev == (unsigned int)(GRID - 1));
    }
    __syncthreads();
    if (!s_last) return;

    // ---- last block: fp64 reduction of 740 partials ----
    double a0 = 0.0, a1 = 0.0, a2 = 0.0, a3 = 0.0;
    for (int i = tid; i < GRID; i += BLK) {
        const float4 v = __ldcg(&g_part[i]);
        a0 += (double)v.x; a1 += (double)v.y;
        a2 += (double)v.z; a3 += (double)v.w;
    }
    double* s0 = (double*)&buf[0][0];     // staging smem is dead; 4 KB reuse
    double* s1 = s0 + BLK;
    double* s2 = s1 + BLK;
    double* s3 = s2 + BLK;
    s0[tid] = a0; s1[tid] = a1; s2[tid] = a2; s3[tid] = a3;
    __syncthreads();
    #pragma unroll
    for (int o = BLK / 2; o > 0; o >>= 1) {
        if (tid < o) {
            s0[tid] += s0[tid + o]; s1[tid] += s1[tid + o];
            s2[tid] += s2[tid + o]; s3[tid] += s3[tid + o];
        }
        __syncthreads();
    }
    if (tid == 0) {
        const float cls = (float)(5.0 * s0[0]);   // lambda_coord
        const float cnf = (float)(5.0 * s1[0]);
        const float cwh = (float)(5.0 * s2[0]);
        const float nob = (float)(0.5 * s3[0]);   // lambda_noobj
        out[0] = cls;
        out[1] = cnf;
        out[2] = cwh;
        out[3] = nob + cls + cnf + cwh;           // total
        g_count = 0;                              // reset for next graph replay
    }
}

extern "C" void kernel_launch(void* const* d_in, const int* in_sizes, int n_in,
                              void* d_out, int out_size)
{
    const float* P = (const float*)d_in[0];   // predictions [B,S,S,30] fp32
    const float* T = (const float*)d_in[1];   // targets     [B,S,S,30] fp32
    float* out = (float*)d_out;               // [cls, conf, center+wh, total]

    yolo_fused<<<GRID, BLK>>>(P, T, out);
}

// round 7
// speedup vs baseline: 1.0688x; 1.0688x over previous
#include <cuda_runtime.h>
#include <cuda_bf16.h>

// YOLOv1 loss — persistent, block-cooperative single-stage cp.async staging.
// 7 blocks/SM (28 warps) — smem-limited, regs capped by __launch_bounds__.
// Evidence (R3-R6): block-cooperative bursts beat warp-autonomous at equal
// warps; warp count is the main DRAM% lever. cp.async frees the 60-reg
// landing zone that capped occupancy in R5.

#define NCELL  (16384 * 7 * 7)       // 802816
#define BLK    128
#define BPSM   7
#define GRID   (148 * BPSM)          // 1036 persistent blocks
#define TILE   128                   // cells per block-tile
#define NTILE  (NCELL / TILE)        // 6272
#define TFL    (TILE * 30)           // floats per tensor per tile (3840)
#define TF4    (TFL / 4)             // float4 per tensor per tile (960)
#define NLD    15                    // float4 staged per thread (2*TF4/BLK)

__device__ float4 g_part[GRID];
__device__ unsigned int g_count = 0;

__device__ __forceinline__ void cp16(float4* dst_smem, const float4* src_gmem) {
    unsigned int d = (unsigned int)__cvta_generic_to_shared(dst_smem);
    asm volatile("cp.async.cg.shared.global [%0], [%1], 16;\n" :: "r"(d), "l"(src_gmem));
}
__device__ __forceinline__ void cp_commit() { asm volatile("cp.async.commit_group;\n"); }
__device__ __forceinline__ void cp_wait0()  { asm volatile("cp.async.wait_group 0;\n"); }

__global__ __launch_bounds__(BLK, BPSM)
void yolo_fused(const float* __restrict__ P,
                const float* __restrict__ T,
                float* __restrict__ out)
{
    __shared__ float buf[2 * TFL];    // [ P(3840) | T(3840) ]  30720 B
    const int tid = threadIdx.x;
    const float CELL = 1.0f / 7.0f;

    float ax = 0.0f, ay = 0.0f, az = 0.0f, aw = 0.0f;

    for (int tile = blockIdx.x; tile < NTILE; tile += GRID) {
        // ---- stage this tile: 1920 x cp.async.cg 16B (contiguous bursts) ----
        {
            const float4* gp = (const float4*)(P + (size_t)tile * TFL);
            const float4* gt = (const float4*)(T + (size_t)tile * TFL);
            float4* b4 = (float4*)buf;
            #pragma unroll
            for (int i = 0; i < NLD; ++i) {
                const int idx = tid + i * BLK;      // 0..1919
                const float4* src = (idx < TF4) ? (gp + idx) : (gt + (idx - TF4));
                cp16(b4 + idx, src);
            }
        }
        cp_commit();
        cp_wait0();
        __syncthreads();              // all threads' copies visible block-wide

        const float* p = buf + tid * 30;
        const float* t = p + TFL;

        const float t0 = t[0], t1 = t[1], t2 = t[2], t3 = t[3], tc = t[4];

        // target corners — faithful to the reference's in-place bug:
        //   xy1 = xy*CELL - wh*0.5 ;  xy2 = xy1*CELL + wh*0.5
        const float twx = t2 * t2, twy = t3 * t3;
        const float tx1 = t0 * CELL - 0.5f * twx;
        const float ty1 = t1 * CELL - 0.5f * twy;
        const float tx2 = tx1 * CELL + 0.5f * twx;
        const float ty2 = ty1 * CELL + 0.5f * twy;
        const float area_t = (tx2 - tx1) * (ty2 - ty1);

        float iou0, iou1;
        #pragma unroll
        for (int b = 0; b < 2; ++b) {
            const float px = p[b * 5 + 0], py = p[b * 5 + 1];
            const float pw = p[b * 5 + 2], ph = p[b * 5 + 3];
            const float pwx = pw * pw, pwy = ph * ph;
            const float x1 = px * CELL - 0.5f * pwx;
            const float y1 = py * CELL - 0.5f * pwy;
            const float x2 = x1 * CELL + 0.5f * pwx;
            const float y2 = y1 * CELL + 0.5f * pwy;
            const float ltx = fmaxf(x1, tx1), lty = fmaxf(y1, ty1);
            const float rbx = fminf(x2, tx2), rby = fminf(y2, ty2);
            const float dx = fmaxf(rbx - ltx, 0.0f);
            const float dy = fmaxf(rby - lty, 0.0f);
            const float inter  = dx * dy;
            const float area_p = (x2 - x1) * (y2 - y1);
            const float v = inter / (area_p + area_t - inter);
            if (b == 0) iou0 = v; else iou1 = v;
        }
        const int b5 = (iou1 > iou0) ? 5 : 0;     // first max wins ties

        // argmax over t[10:30] — order-preserving tree (adjacent pairing keeps
        // index sets contiguous & ordered -> exact first-max semantics, depth 5)
        float av[10]; int ak[10];
        #pragma unroll
        for (int k = 0; k < 10; ++k) {
            const float a = t[10 + 2 * k], b = t[11 + 2 * k];
            const bool g = b > a;
            av[k] = g ? b : a;
            ak[k] = 10 + 2 * k + (g ? 1 : 0);
        }
        #pragma unroll
        for (int k = 0; k < 5; ++k) {
            const bool g = av[2 * k + 1] > av[2 * k];
            av[k] = g ? av[2 * k + 1] : av[2 * k];
            ak[k] = g ? ak[2 * k + 1] : ak[2 * k];
        }
        { const bool g = av[1] > av[0]; av[0] = g ? av[1] : av[0]; ak[0] = g ? ak[1] : ak[0]; }
        { const bool g = av[3] > av[2]; av[2] = g ? av[3] : av[2]; ak[2] = g ? ak[3] : ak[2]; }
        { const bool g = av[2] > av[0]; av[0] = g ? av[2] : av[0]; ak[0] = g ? ak[2] : ak[0]; }
        { const bool g = av[4] > av[0]; av[0] = g ? av[4] : av[0]; ak[0] = g ? ak[4] : ak[0]; }
        const int   kcol = ak[0];
        const float tmax = av[0];     // == t[kcol]

        const bool obj = (tc == 1.0f);
        const bool noo = (tc == 0.0f);

        const float dk = p[kcol]   - tmax;
        const float dc = p[b5 + 4] - t[b5 + 4];
        const float d0 = p[b5 + 0] - t[b5 + 0];
        const float d1 = p[b5 + 1] - t[b5 + 1];
        const float d2 = p[b5 + 2] - t[b5 + 2];
        const float d3 = p[b5 + 3] - t[b5 + 3];
        const float d4 = p[4] - tc;
        const float d9 = p[9] - t[9];

        if (obj) {
            ax += dk * dk;                                   // cls
            ay += dc * dc;                                   // conf
            az += d0 * d0 + d1 * d1 + d2 * d2 + d3 * d3;     // center+wh
        }
        if (noo) aw += d4 * d4 + d9 * d9;                    // noobj

        __syncthreads();              // all reads done before next stage write
    }

    // ---- block reduce (once per block) ----
    #pragma unroll
    for (int o = 16; o > 0; o >>= 1) {
        ax += __shfl_down_sync(0xffffffffu, ax, o);
        ay += __shfl_down_sync(0xffffffffu, ay, o);
        az += __shfl_down_sync(0xffffffffu, az, o);
        aw += __shfl_down_sync(0xffffffffu, aw, o);
    }
    __shared__ float4 wsum[BLK / 32];
    __shared__ bool s_last;
    if ((tid & 31) == 0) wsum[tid >> 5] = make_float4(ax, ay, az, aw);
    __syncthreads();
    if (tid == 0) {
        float4 sv = wsum[0];
        #pragma unroll
        for (int w = 1; w < BLK / 32; ++w) {
            sv.x += wsum[w].x; sv.y += wsum[w].y;
            sv.z += wsum[w].z; sv.w += wsum[w].w;
        }
        __stcg(&g_part[blockIdx.x], sv);
        __threadfence();
        unsigned int prev = atomicAdd(&g_count, 1u);
        s_last = (prev == (unsigned int)(GRID - 1));
    }
    __syncthreads();
    if (!s_last) return;

    // ---- last block: fp64 reduction of 1036 partials ----
    double a0 = 0.0, a1 = 0.0, a2 = 0.0, a3 = 0.0;
    for (int i = tid; i < GRID; i += BLK) {
        const float4 v = __ldcg(&g_part[i]);
        a0 += (double)v.x; a1 += (double)v.y;
        a2 += (double)v.z; a3 += (double)v.w;
    }
    double* s0 = (double*)buf;        // staging smem is dead; reuse 4 KB
    double* s1 = s0 + BLK;
    double* s2 = s1 + BLK;
    double* s3 = s2 + BLK;
    s0[tid] = a0; s1[tid] = a1; s2[tid] = a2; s3[tid] = a3;
    __syncthreads();
    #pragma unroll
    for (int o = BLK / 2; o > 0; o >>= 1) {
        if (tid < o) {
            s0[tid] += s0[tid + o]; s1[tid] += s1[tid + o];
            s2[tid] += s2[tid + o]; s3[tid] += s3[tid + o];
        }
        __syncthreads();
    }
    if (tid == 0) {
        const float cls = (float)(5.0 * s0[0]);   // lambda_coord
        const float cnf = (float)(5.0 * s1[0]);
        const float cwh = (float)(5.0 * s2[0]);
        const float nob = (float)(0.5 * s3[0]);   // lambda_noobj
        out[0] = cls;
        out[1] = cnf;
        out[2] = cwh;
        out[3] = nob + cls + cnf + cwh;           // total
        g_count = 0;                              // reset for next graph replay
    }
}

extern "C" void kernel_launch(void* const* d_in, const int* in_sizes, int n_in,
                              void* d_out, int out_size)
{
    const float* P = (const float*)d_in[0];   // predictions [B,S,S,30] fp32
    const float* T = (const float*)d_in[1];   // targets     [B,S,S,30] fp32
    float* out = (float*)d_out;               // [cls, conf, center+wh, total]

    yolo_fused<<<GRID, BLK>>>(P, T, out);
}